// round 1
// baseline (speedup 1.0000x reference)
#include <cuda_runtime.h>

#define BATCH 1024
#define RC 64
#define NL 24
#define QL 128
#define TB 8                    // batch rows per compute block
#define NCOMP (BATCH / TB)      // 128 compute blocks
#define NCOPY 896
#define NBLOCKS (NCOMP + NCOPY)
#define NTHREADS 256
#define NQ ((size_t)NL * BATCH * RC * QL)   // 201326592 queue elements

__device__ __forceinline__ float sigf(float x) { return 1.0f / (1.0f + __expf(-x)); }

__global__ void __launch_bounds__(NTHREADS)
wave_decoder_kernel(const float* __restrict__ x,
                    const float* __restrict__ features,
                    const float* __restrict__ queues,
                    const float* __restrict__ fc_h_w,
                    const float* __restrict__ fc_h_b,
                    const float* __restrict__ fc_c_w,
                    const float* __restrict__ fc_c_b,
                    const float* __restrict__ conv_w,
                    const float* __restrict__ conv_b,
                    const float* __restrict__ fc1_w,
                    const float* __restrict__ fc1_b,
                    const float* __restrict__ fc2_w,
                    const float* __restrict__ fc2_b,
                    float* __restrict__ out)
{
    if (blockIdx.x >= NCOMP) {
        // ------------------------------------------------------------------
        // COPY BLOCKS: queues (.., 128) -> out queue region (.., 129), t<128
        // ------------------------------------------------------------------
        const float4* __restrict__ src = (const float4*)queues;
        float* __restrict__ dstq = out + BATCH;
        size_t tid    = (size_t)(blockIdx.x - NCOMP) * NTHREADS + threadIdx.x;
        size_t stride = (size_t)NCOPY * NTHREADS;
        const size_t n4 = NQ / 4;
        #pragma unroll 2
        for (size_t i4 = tid; i4 < n4; i4 += stride) {
            float4 v = src[i4];
            size_t e   = i4 * 4;
            size_t row = e >> 7;          // (layer*B + b)*RC + r
            unsigned t = (unsigned)(e & 127);
            float* p = dstq + row * 129 + t;
            p[0] = v.x; p[1] = v.y; p[2] = v.z; p[3] = v.w;
        }
        return;
    }

    // ----------------------------------------------------------------------
    // COMPUTE BLOCKS: recurrent WaveNet cell for TB batch rows
    // thread j = threadIdx.x owns output channel j (0..255) of conv / fc1
    // ----------------------------------------------------------------------
    __shared__ __align__(16) float s_h[TB][RC];
    __shared__ __align__(16) float s_c[TB][RC];
    __shared__ __align__(16) float s_prev[TB][RC];
    __shared__ float s_co[TB][4 * RC];

    const int tid = threadIdx.x;
    const int b0  = blockIdx.x * TB;
    const int j   = tid;

    // ---- initial h, c = tanh(inp @ W^T + b), inp = [x, features] (33) ----
    for (int idx = tid; idx < TB * RC; idx += NTHREADS) {
        int t = idx >> 6, r = idx & 63;
        int b = b0 + t;
        const float* wh = fc_h_w + r * 33;
        const float* wc = fc_c_w + r * 33;
        float ah = fc_h_b[r], ac = fc_c_b[r];
        float xv = x[b];
        ah += xv * wh[0];
        ac += xv * wc[0];
        const float* fb = features + b * 32;
        #pragma unroll
        for (int k = 0; k < 32; k++) {
            float f = fb[k];
            ah += f * wh[1 + k];
            ac += f * wc[1 + k];
        }
        s_h[t][r] = tanhf(ah);
        s_c[t][r] = tanhf(ac);
    }

    float yacc[TB];
    #pragma unroll
    for (int t = 0; t < TB; t++) yacc[t] = fc1_b[j];
    __syncthreads();

    float* __restrict__ outq = out + BATCH;

    for (int i = 0; i < NL; i++) {
        const int d = 1 << (i & 7);

        // ---- load dilated queue slice; write entry_h at t = 128 ----
        for (int idx = tid; idx < TB * RC; idx += NTHREADS) {
            int t = idx >> 6, r = idx & 63;
            int b = b0 + t;
            size_t rowi = (size_t)(i * BATCH + b) * RC + r;
            s_prev[t][r] = queues[rowi * QL + (QL - d)];
            outq[rowi * 129 + QL] = s_h[t][r];
        }
        __syncthreads();

        // ---- co[t][j] = prev @ W0^T + h @ W1^T + b  (weights in regs) ----
        float acc[TB];
        {
            float bias = conv_b[i * 256 + j];
            #pragma unroll
            for (int t = 0; t < TB; t++) acc[t] = bias;
        }
        const float4* __restrict__ wrow =
            (const float4*)(conv_w + (size_t)(i * 256 + j) * 128); // [r][2] interleaved
        #pragma unroll 4
        for (int rc = 0; rc < RC; rc += 4) {
            float4 wa = wrow[rc >> 1];       // w0[rc], w1[rc], w0[rc+1], w1[rc+1]
            float4 wb = wrow[(rc >> 1) + 1];
            #pragma unroll
            for (int t = 0; t < TB; t++) {
                float4 p  = *(const float4*)&s_prev[t][rc];
                float4 hh = *(const float4*)&s_h[t][rc];
                float a = acc[t];
                a += p.x * wa.x + hh.x * wa.y;
                a += p.y * wa.z + hh.y * wa.w;
                a += p.z * wb.x + hh.z * wb.y;
                a += p.w * wb.z + hh.w * wb.w;
                acc[t] = a;
            }
        }
        #pragma unroll
        for (int t = 0; t < TB; t++) s_co[t][j] = acc[t];
        __syncthreads();

        // ---- gate update ----
        for (int idx = tid; idx < TB * RC; idx += NTHREADS) {
            int t = idx >> 6, r = idx & 63;
            float ig = s_co[t][r];
            float cf = s_co[t][RC + r];
            float cg = s_co[t][2 * RC + r];
            float eg = s_co[t][3 * RC + r];
            float c = sigf(ig) * s_c[t][r] + tanhf(cf) * sigf(cg);
            s_c[t][r] = c;
            s_h[t][r] = sigf(eg) * tanhf(c);
        }
        __syncthreads();

        // ---- incremental fc1: yacc[t] += h[t] @ fc1_w[j, i*64 : i*64+64] ----
        const float4* __restrict__ f1 =
            (const float4*)(fc1_w + (size_t)j * (NL * RC) + i * RC);
        #pragma unroll 4
        for (int rc = 0; rc < RC; rc += 4) {
            float4 w = f1[rc >> 2];
            #pragma unroll
            for (int t = 0; t < TB; t++) {
                float4 hh = *(const float4*)&s_h[t][rc];
                yacc[t] += hh.x * w.x + hh.y * w.y + hh.z * w.z + hh.w * w.w;
            }
        }
        // no barrier needed: next iteration's load only reads s_h / writes
        // s_prev, both safe until after the next two barriers
    }

    // ---- fc2: h_hat[b] = relu(y) @ fc2_w^T + fc2_b ----
    #pragma unroll
    for (int t = 0; t < TB; t++)
        s_co[t][j] = fmaxf(yacc[t], 0.0f) * fc2_w[j];
    __syncthreads();

    int w = tid >> 5, lane = tid & 31;   // 8 warps == TB rows
    float s = 0.0f;
    #pragma unroll
    for (int k = 0; k < 8; k++) s += s_co[w][lane + k * 32];
    #pragma unroll
    for (int o = 16; o > 0; o >>= 1) s += __shfl_xor_sync(0xffffffffu, s, o);
    if (lane == 0) out[b0 + w] = s + fc2_b[0];
}

extern "C" void kernel_launch(void* const* d_in, const int* in_sizes, int n_in,
                              void* d_out, int out_size)
{
    const float* x        = (const float*)d_in[0];
    const float* features = (const float*)d_in[1];
    const float* queues   = (const float*)d_in[2];
    const float* fc_h_w   = (const float*)d_in[3];
    const float* fc_h_b   = (const float*)d_in[4];
    const float* fc_c_w   = (const float*)d_in[5];
    const float* fc_c_b   = (const float*)d_in[6];
    const float* conv_w   = (const float*)d_in[7];
    const float* conv_b   = (const float*)d_in[8];
    const float* fc1_w    = (const float*)d_in[9];
    const float* fc1_b    = (const float*)d_in[10];
    const float* fc2_w    = (const float*)d_in[11];
    const float* fc2_b    = (const float*)d_in[12];
    float* out = (float*)d_out;

    wave_decoder_kernel<<<NBLOCKS, NTHREADS>>>(
        x, features, queues, fc_h_w, fc_h_b, fc_c_w, fc_c_b,
        conv_w, conv_b, fc1_w, fc1_b, fc2_w, fc2_b, out);
}